// round 4
// baseline (speedup 1.0000x reference)
#include <cuda_runtime.h>
#include <cstdint>

// Model_NPZD_68401649156380 — R4: cp.async double-buffered pipeline.
// 128 blocks x 256 threads; each block: 16 batches = 4 stages x 4 batches.
// Stage g+1 forcing is gathered via 4B cp.async (compacting stride-12B reads)
// WHILE stage g runs the 56-step Euler recurrence -> continuous DRAM demand.
//
// idx(w,s) = 168w + 3s (exact) => compact j = 56w + s, col = 3j, j < 2912.

#define NB      2048
#define NWK     52
#define NHRS    8760
#define DT      0.125f
#define NT      256
#define GPER    4                     // batches per stage
#define NSTAGE  4                     // stages per block
#define GRID    (NB / (GPER * NSTAGE))   // 128
#define NJ      2912
#define WPAD    57                    // padded per-w stride (float2)
#define SBAT    (NWK * WPAD)          // 2964 float2 per batch
#define STAGEF2 (GPER * SBAT)         // 11856 float2 per stage buffer
#define SMEM_BYTES (2 * STAGEF2 * (int)sizeof(float2))   // 189,696 B

__device__ __forceinline__ void issue_stage(
    const float* __restrict__ gf, const float* __restrict__ gm,
    int bbase, float2* buf, int tid)
{
    uint32_t base = (uint32_t)__cvta_generic_to_shared(buf);
    #pragma unroll 2
    for (int i = tid; i < GPER * NJ; i += NT) {
        int g = i / NJ;
        int j = i - g * NJ;
        int w = j / 56;
        int s = j - w * 56;
        const float* fp = gf + (size_t)(bbase + g) * NHRS + 3 * j;
        const float* mp = gm + (size_t)(bbase + g) * NHRS + 3 * j;
        uint32_t dst = base + (uint32_t)((g * SBAT + w * WPAD + s) * 8);
        asm volatile("cp.async.ca.shared.global [%0], [%1], 4;\n"
                     :: "r"(dst), "l"(fp) : "memory");
        asm volatile("cp.async.ca.shared.global [%0], [%1], 4;\n"
                     :: "r"(dst + 4), "l"(mp) : "memory");
    }
    asm volatile("cp.async.commit_group;\n" ::: "memory");
}

__global__ __launch_bounds__(NT, 1) void npzd_kernel(
    const float* __restrict__ X_in,     // (B, 52, 5, 1)
    const float* __restrict__ gf,       // (B, 8760)
    const float* __restrict__ gm,       // (B, 8760)
    const float* __restrict__ pv,       // (B, 10)
    float* __restrict__ out)            // (B, 52, 4, 8)
{
    extern __shared__ float2 sbuf[];    // [2][STAGEF2]
    const int tid  = threadIdx.x;
    const int bblk = blockIdx.x * (GPER * NSTAGE);

    // Prologue: gather stage 0 synchronously
    issue_stage(gf, gm, bblk, sbuf, tid);
    asm volatile("cp.async.wait_group 0;\n" ::: "memory");
    __syncthreads();

    #pragma unroll 1
    for (int st = 0; st < NSTAGE; ++st) {
        float2* cur = sbuf + ((st    ) & 1) * STAGEF2;
        float2* nxt = sbuf + ((st + 1) & 1) * STAGEF2;
        const int bbase = bblk + st * GPER;

        // Kick off next stage's gather before computing this one
        if (st + 1 < NSTAGE)
            issue_stage(gf, gm, bbase + GPER, nxt, tid);

        // ---- compute: 208 threads, one ODE each ----
        float o[4][8];
        if (tid < GPER * NWK) {
            const int g = tid / NWK;
            const int w = tid - g * NWK;
            const int b = bbase + g;

            const float* p = pv + b * 10;
            const float chiC   = p[0];
            const float rho2   = p[1] * 2.0f;
            const float gam01  = p[2] * 0.1f;
            const float lam005 = p[3] * 0.05f;
            const float eps01  = p[4] * 0.1f;
            const float alp03  = p[5] * 0.3f;
            const float bet06  = p[6] * 0.6f;
            const float eta015 = p[7] * 0.15f;
            const float phi04  = p[8] * 0.4f;
            const float zet01  = p[9] * 0.1f;
            const float rem    = 1.0f - alp03 - bet06;

            const float* xi = X_in + ((size_t)(b * NWK + w)) * 5;
            float N = xi[1], P = xi[2], Z = xi[3], D = xi[4];

            const float2* sp = cur + g * SBAT + w * WPAD;

            o[0][0] = N; o[1][0] = P; o[2][0] = Z; o[3][0] = D;
            int s = 0;
            #pragma unroll 1
            for (int k = 1; k <= 7; ++k) {
                #pragma unroll
                for (int i = 0; i < 8; ++i, ++s) {
                    float2 fm = sp[s];
                    float ft = fm.x, mt = fm.y;

                    float Pc = fmaxf(0.01f, P);
                    float Zc = fmaxf(0.01f, Z);
                    float gN = N / (chiC + N);
                    float zg = rho2 * (1.0f - __expf(-lam005 * Pc)) * Zc;
                    float up = gN * ft * Pc;                    // Vm = 1

                    float Nn = N + DT * (-up + alp03 * zg + eps01 * P + gam01 * Z
                                         + phi04 * D + mt * (8.0f - N));   // Q0=8
                    float Pn = P + DT * (up - zg - eps01 * P - eta015 * P - mt * P);
                    float Zn = Z + DT * (bet06 * zg - gam01 * Z - mt * Z);
                    float Dn = D + DT * (eta015 * P + rem * zg - phi04 * D
                                         - zet01 * D - mt * D);
                    N = Nn; P = Pn; Z = Zn; D = Dn;
                }
                o[0][k] = N; o[1][k] = P; o[2][k] = Z; o[3][k] = D;
            }
        }
        __syncthreads();   // all reads of cur done; safe to reuse as obuf

        // ---- transpose through smem, coalesced output stores ----
        float* obuf = (float*)cur;       // 208*33 floats = 27.4 KB, fits
        if (tid < GPER * NWK) {
            float* ob = obuf + tid * 33;
            #pragma unroll
            for (int c = 0; c < 4; ++c)
                #pragma unroll
                for (int k = 0; k < 8; ++k)
                    ob[c * 8 + k] = o[c][k];
        }
        __syncthreads();

        float* outb = out + (size_t)bbase * (NWK * 32);
        #pragma unroll
        for (int i = tid; i < GPER * NWK * 32; i += NT) {
            int t2 = i >> 5;
            int m  = i & 31;
            outb[i] = obuf[t2 * 33 + m];
        }

        // Drain next stage's gather before flipping buffers
        if (st + 1 < NSTAGE)
            asm volatile("cp.async.wait_group 0;\n" ::: "memory");
        __syncthreads();
    }
}

extern "C" void kernel_launch(void* const* d_in, const int* in_sizes, int n_in,
                              void* d_out, int out_size)
{
    (void)in_sizes; (void)n_in; (void)out_size;
    const float* X_in = (const float*)d_in[0];
    const float* gf   = (const float*)d_in[1];
    const float* gm   = (const float*)d_in[2];
    const float* pvv  = (const float*)d_in[3];
    float* out        = (float*)d_out;

    cudaFuncSetAttribute(npzd_kernel,
                         cudaFuncAttributeMaxDynamicSharedMemorySize,
                         SMEM_BYTES);
    npzd_kernel<<<GRID, NT, SMEM_BYTES>>>(X_in, gf, gm, pvv, out);
}

// round 5
// speedup vs baseline: 1.1105x; 1.1105x over previous
#include <cuda_runtime.h>
#include <cstdint>

// Model_NPZD_68401649156380 — R5: fine-grained cp.async chunk pipeline.
// Block = 256 threads, G=4 batches (208 ODE threads). Forcing for the 56
// steps is gathered in 7 chunks of 8 steps through a 3-slot cp.async ring:
// while chunk c is computed, chunk c+2 is in flight -> continuous DRAM demand.
//
// idx(w,s) = 168w + 3s (exact). Chunk c, step i: col = 168w + 24c + 3i.

#define NB      2048
#define NWK     52
#define NHRS    8760
#define DT      0.125f
#define NT      256
#define G       4                      // batches per block
#define NCOMP   (G * NWK)              // 208
#define NCH     7                      // chunks (8 steps each)
#define NSLOT   3                      // ring depth
#define IPAD    9                      // per-(w) chunk stride in float2 (8+1)
#define SLOTF2  (G * NWK * IPAD)       // 1872 float2 per slot
#define SMEM_F2 (NSLOT * SLOTF2)       // 5616 float2 = 44928 B
#define CH_ELE  (G * NWK * 8)          // 1664 forcing pairs per chunk

__device__ __forceinline__ void issue_chunk(
    const float* __restrict__ gf, const float* __restrict__ gm,
    int b0, int c, float2* slot, int tid)
{
    uint32_t base = (uint32_t)__cvta_generic_to_shared(slot);
    #pragma unroll
    for (int e = tid; e < CH_ELE; e += NT) {
        int g = e / (NWK * 8);
        int r = e - g * (NWK * 8);
        int w = r >> 3;
        int i = r & 7;
        int col = 168 * w + 24 * c + 3 * i;
        const float* fp = gf + (size_t)(b0 + g) * NHRS + col;
        const float* mp = gm + (size_t)(b0 + g) * NHRS + col;
        uint32_t dst = base + (uint32_t)(((g * NWK + w) * IPAD + i) * 8);
        asm volatile("cp.async.ca.shared.global [%0], [%1], 4;\n"
                     :: "r"(dst), "l"(fp) : "memory");
        asm volatile("cp.async.ca.shared.global [%0], [%1], 4;\n"
                     :: "r"(dst + 4), "l"(mp) : "memory");
    }
    asm volatile("cp.async.commit_group;\n" ::: "memory");
}

__global__ __launch_bounds__(NT, 4) void npzd_kernel(
    const float* __restrict__ X_in,     // (B, 52, 5, 1)
    const float* __restrict__ gf,       // (B, 8760)
    const float* __restrict__ gm,       // (B, 8760)
    const float* __restrict__ pv,       // (B, 10)
    float* __restrict__ out)            // (B, 52, 4, 8)
{
    extern __shared__ float2 ring[];    // [NSLOT][G][52][IPAD]
    const int tid = threadIdx.x;
    const int b0  = blockIdx.x * G;

    // Prime the pipeline: chunks 0 and 1 in flight.
    issue_chunk(gf, gm, b0, 0, ring + 0 * SLOTF2, tid);
    issue_chunk(gf, gm, b0, 1, ring + 1 * SLOTF2, tid);

    // Per-thread state/params load overlaps with the first gathers.
    const int g = tid / NWK;            // valid when tid < NCOMP
    const int w = tid - g * NWK;
    const int b = b0 + g;

    float chiC=0, rho2=0, gam01=0, lam005=0, eps01=0,
          alp03=0, bet06=0, eta015=0, phi04=0, zet01=0, rem=0;
    float N=0, P=0, Z=0, D=0;
    if (tid < NCOMP) {
        const float* p = pv + b * 10;
        chiC   = p[0];
        rho2   = p[1] * 2.0f;
        gam01  = p[2] * 0.1f;
        lam005 = p[3] * 0.05f;
        eps01  = p[4] * 0.1f;
        alp03  = p[5] * 0.3f;
        bet06  = p[6] * 0.6f;
        eta015 = p[7] * 0.15f;
        phi04  = p[8] * 0.4f;
        zet01  = p[9] * 0.1f;
        rem    = 1.0f - alp03 - bet06;

        const float* xi = X_in + ((size_t)(b * NWK + w)) * 5;
        N = xi[1]; P = xi[2]; Z = xi[3]; D = xi[4];
    }

    float o[4][8];
    o[0][0] = N; o[1][0] = P; o[2][0] = Z; o[3][0] = D;

    #pragma unroll 1
    for (int c = 0; c < NCH; ++c) {
        // chunk c must have landed; groups in flight afterwards: {c+1}
        asm volatile("cp.async.wait_group 1;\n" ::: "memory");
        __syncthreads();   // also: everyone done reading slot (c-1)%3 last iter

        // keep the pipe full: issue chunk c+2 into the slot just freed
        if (c + 2 < NCH)
            issue_chunk(gf, gm, b0, c + 2, ring + ((c + 2) % NSLOT) * SLOTF2, tid);

        if (tid < NCOMP) {
            const float2* sp = ring + (c % NSLOT) * SLOTF2
                             + (g * NWK + w) * IPAD;
            #pragma unroll
            for (int i = 0; i < 8; ++i) {
                float2 fm = sp[i];
                float ft = fm.x, mt = fm.y;

                float Pc = fmaxf(0.01f, P);
                float Zc = fmaxf(0.01f, Z);
                float gN = N / (chiC + N);
                float zg = rho2 * (1.0f - __expf(-lam005 * Pc)) * Zc;
                float up = gN * ft * Pc;                    // Vm = 1

                float Nn = N + DT * (-up + alp03 * zg + eps01 * P + gam01 * Z
                                     + phi04 * D + mt * (8.0f - N));   // Q0=8
                float Pn = P + DT * (up - zg - eps01 * P - eta015 * P - mt * P);
                float Zn = Z + DT * (bet06 * zg - gam01 * Z - mt * Z);
                float Dn = D + DT * (eta015 * P + rem * zg - phi04 * D
                                     - zet01 * D - mt * D);
                N = Nn; P = Pn; Z = Zn; D = Dn;
            }
            o[0][c + 1] = N; o[1][c + 1] = P; o[2][c + 1] = Z; o[3][c + 1] = D;
        }
    }
    __syncthreads();   // all ring reads done; reuse smem for output transpose

    // ---- transpose through smem, coalesced output stores ----
    float* obuf = (float*)ring;          // 208*33 floats = 27.4 KB, fits
    if (tid < NCOMP) {
        float* ob = obuf + tid * 33;     // pad 33: conflict-free
        #pragma unroll
        for (int cc = 0; cc < 4; ++cc)
            #pragma unroll
            for (int k = 0; k < 8; ++k)
                ob[cc * 8 + k] = o[cc][k];
    }
    __syncthreads();

    // block output region: 208*32 = 6656 contiguous floats
    float* outb = out + (size_t)blockIdx.x * (NCOMP * 32);
    #pragma unroll
    for (int i = tid; i < NCOMP * 32; i += NT) {
        int t2 = i >> 5;
        int m  = i & 31;
        outb[i] = obuf[t2 * 33 + m];
    }
}

extern "C" void kernel_launch(void* const* d_in, const int* in_sizes, int n_in,
                              void* d_out, int out_size)
{
    (void)in_sizes; (void)n_in; (void)out_size;
    const float* X_in = (const float*)d_in[0];
    const float* gf   = (const float*)d_in[1];
    const float* gm   = (const float*)d_in[2];
    const float* pvv  = (const float*)d_in[3];
    float* out        = (float*)d_out;

    cudaFuncSetAttribute(npzd_kernel,
                         cudaFuncAttributeMaxDynamicSharedMemorySize,
                         SMEM_F2 * (int)sizeof(float2));
    npzd_kernel<<<NB / G, NT, SMEM_F2 * (int)sizeof(float2)>>>(
        X_in, gf, gm, pvv, out);
}